// round 8
// baseline (speedup 1.0000x reference)
#include <cuda_runtime.h>
#include <cuda_bf16.h>
#include <cstdint>

#define NUM_TAGS 48
#define SEQ_LEN  512
#define BATCH    1024
#define CHUNK    8
#define HALF     256
#define NCH      (HALF / CHUNK)     // 32 chunks per half

__device__ float    g_nll[BATCH];
__device__ float    g_vec[BATCH][2][NUM_TAGS];
__device__ float    g_part[BATCH][2][4];     // [C, score, -, -]
__device__ unsigned g_pair[BATCH];
__device__ unsigned g_count = 0;

// ---- packed f32x2 helpers (Blackwell FFMA2 path, PTX-only) ------------------
__device__ __forceinline__ void fma2(uint64_t& d, uint64_t a, uint64_t b) {
    asm("fma.rn.f32x2 %0, %1, %2, %0;" : "+l"(d) : "l"(a), "l"(b));
}
__device__ __forceinline__ uint64_t add2(uint64_t a, uint64_t b) {
    uint64_t d;
    asm("add.rn.f32x2 %0, %1, %2;" : "=l"(d) : "l"(a), "l"(b));
    return d;
}
__device__ __forceinline__ uint64_t pack2(float lo, float hi) {
    uint64_t d;
    asm("mov.b64 %0, {%1, %2};" : "=l"(d) : "f"(lo), "f"(hi));
    return d;
}
__device__ __forceinline__ float lo2(uint64_t v) { return __uint_as_float((uint32_t)v); }
__device__ __forceinline__ float hi2(uint64_t v) { return __uint_as_float((uint32_t)(v >> 32)); }

__device__ __forceinline__ void cp16(uint32_t saddr, const void* g) {
    asm volatile("cp.async.cg.shared.global [%0], [%1], 16;" :: "r"(saddr), "l"(g));
}

// grid = 2*BATCH single-warp CTAs. bid>>1 = batch, bid&1 = half (0 fwd, 1 bwd).
__global__ __launch_bounds__(32)
void crf_split_kernel(const float* __restrict__ emissions,
                      const float* __restrict__ transitions,
                      const int*   __restrict__ tags,
                      const int*   __restrict__ mask,
                      float*       __restrict__ out)
{
    const int lane = threadIdx.x;
    const int b    = blockIdx.x >> 1;
    const int half = blockIdx.x & 1;
    const int h    = lane >> 4;     // 24-wide input half: [24h, 24h+24)
    const int q    = lane & 15;     // owned output triple {3q,3q+1,3q+2}
    const int j0   = 3 * q;
    const int i0   = 24 * h;

    __shared__ __align__(16) float swbuf[2][NUM_TAGS];        // state ping-pong
    __shared__ __align__(16) float sem[2][CHUNK * NUM_TAGS];  // emission chunks
    __shared__ int stags[SEQ_LEN];
    __shared__ int smask[SEQ_LEN];

    const float* em_b   = emissions + (size_t)b * SEQ_LEN * NUM_TAGS;
    const int*   tags_b = tags + b * SEQ_LEN;
    const int*   mask_b = mask + b * SEQ_LEN;

    // --- stage emission chunk 0 (fwd: t=0..7, bwd: t=504..511) ------------------
    {
        const float* src = em_b + (half == 0 ? 0 : (size_t)(SEQ_LEN - CHUNK) * NUM_TAGS);
        uint32_t dst = (uint32_t)__cvta_generic_to_shared(&sem[0][0]);
        #pragma unroll
        for (int r = 0; r < 3; r++)
            cp16(dst + lane * 16 + r * 512, src + lane * 4 + r * 128);
        asm volatile("cp.async.commit_group;");
    }

    // --- tags / mask to shared -----------------------------------------------------
    #pragma unroll
    for (int r = 0; r < 4; r++) {
        ((int4*)stags)[lane + 32 * r] = ((const int4*)tags_b)[lane + 32 * r];
        ((int4*)smask)[lane + 32 * r] = ((const int4*)mask_b)[lane + 32 * r];
    }
    __syncwarp();

    // --- gold-path score for this half (overlaps chunk-0 latency) -------------------
    float sc = 0.0f;
    {
        const int t0 = (half == 0) ? 1 : HALF;
        const int t1 = (half == 0) ? HALF : SEQ_LEN;
        #pragma unroll 4
        for (int t = t0 + lane; t < t1; t += 32) {
            int tc = stags[t], tp = stags[t - 1];
            if (smask[t])
                sc += em_b[(size_t)t * NUM_TAGS + tc] + transitions[tp * NUM_TAGS + tc];
        }
        #pragma unroll
        for (int off = 16; off; off >>= 1)
            sc += __shfl_xor_sync(0xffffffffu, sc, off);
        if (half == 0) sc += __shfl_sync(0xffffffffu,
                              (lane == 0) ? em_b[stags[0]] : 0.0f, 0);
    }

    float C = 0.0f;
    float f0, f1, f2;   // final normalized state triple

    if (half == 0) {
        // ================= FORWARD: w <- (E^T w) . exp(e_t), t = 0..255 ==========
        uint64_t Ec[36];
        #pragma unroll
        for (int c = 0; c < 3; c++)
            #pragma unroll
            for (int k = 0; k < 12; k++)
                Ec[c * 12 + k] = pack2(__expf(transitions[(i0 + 2 * k    ) * NUM_TAGS + j0 + c]),
                                       __expf(transitions[(i0 + 2 * k + 1) * NUM_TAGS + j0 + c]));

        float w0 = (q == 0) ? 1.0f : 0.0f, w1 = 0.0f, w2 = 0.0f;
        swbuf[0][j0] = w0; swbuf[0][j0 + 1] = w1; swbuf[0][j0 + 2] = w2;
        __syncwarp();

        float carry_inv = 1.0f;
        for (int c = 0; c < NCH; c++) {
            if (c + 1 < NCH) {
                uint32_t dst = (uint32_t)__cvta_generic_to_shared(&sem[(c + 1) & 1][0]);
                const float* src = em_b + (size_t)(c + 1) * CHUNK * NUM_TAGS;
                #pragma unroll
                for (int r = 0; r < 3; r++)
                    cp16(dst + lane * 16 + r * 512, src + lane * 4 + r * 128);
            }
            asm volatile("cp.async.commit_group;");
            asm volatile("cp.async.wait_group 1;");
            __syncwarp();

            const float* eb = sem[c & 1];
            float eE[CHUNK][3];
            #pragma unroll
            for (int u = 0; u < CHUNK; u++) {
                eE[u][0] = __expf(eb[u * NUM_TAGS + j0]);
                eE[u][1] = __expf(eb[u * NUM_TAGS + j0 + 1]);
                eE[u][2] = __expf(eb[u * NUM_TAGS + j0 + 2]);
            }

            const int4 ma = ((const int4*)(smask + c * CHUNK))[0];
            const int4 mbq = ((const int4*)(smask + c * CHUNK))[1];
            const int mall = ma.x & ma.y & ma.z & ma.w & mbq.x & mbq.y & mbq.z & mbq.w;

            if (mall) {
                eE[0][0] *= carry_inv; eE[0][1] *= carry_inv; eE[0][2] *= carry_inv;
                #pragma unroll
                for (int u = 0; u < CHUNK; u++) {
                    const ulonglong2* wv = (const ulonglong2*)(&swbuf[u & 1][i0]);
                    uint64_t a0[3] = {0,0,0}, a1[3] = {0,0,0};
                    #pragma unroll
                    for (int r = 0; r < 6; r++) {
                        ulonglong2 W = wv[r];
                        #pragma unroll
                        for (int cc = 0; cc < 3; cc++) {
                            fma2(a0[cc], W.x, Ec[cc * 12 + 2 * r]);
                            fma2(a1[cc], W.y, Ec[cc * 12 + 2 * r + 1]);
                        }
                    }
                    float* wd = swbuf[(u & 1) ^ 1];
                    #pragma unroll
                    for (int cc = 0; cc < 3; cc++) {
                        uint64_t s = add2(a0[cc], a1[cc]);
                        float d = lo2(s) + hi2(s);
                        d += __shfl_xor_sync(0xffffffffu, d, 16);
                        d *= eE[u][cc];
                        if (cc == 0) w0 = d; else if (cc == 1) w1 = d; else w2 = d;
                        wd[j0 + cc] = d;
                    }
                    asm volatile("" ::: "memory");
                }
            } else {
                w0 *= carry_inv; w1 *= carry_inv; w2 *= carry_inv;
                carry_inv = 1.0f;
                swbuf[0][j0] = w0; swbuf[0][j0 + 1] = w1; swbuf[0][j0 + 2] = w2;
                __syncwarp();
                #pragma unroll
                for (int u = 0; u < CHUNK; u++) {
                    const ulonglong2* wv = (const ulonglong2*)(&swbuf[u & 1][i0]);
                    uint64_t a0[3] = {0,0,0}, a1[3] = {0,0,0};
                    #pragma unroll
                    for (int r = 0; r < 6; r++) {
                        ulonglong2 W = wv[r];
                        #pragma unroll
                        for (int cc = 0; cc < 3; cc++) {
                            fma2(a0[cc], W.x, Ec[cc * 12 + 2 * r]);
                            fma2(a1[cc], W.y, Ec[cc * 12 + 2 * r + 1]);
                        }
                    }
                    int m = smask[c * CHUNK + u];
                    float nv[3];
                    #pragma unroll
                    for (int cc = 0; cc < 3; cc++) {
                        uint64_t s = add2(a0[cc], a1[cc]);
                        float d = lo2(s) + hi2(s);
                        d += __shfl_xor_sync(0xffffffffu, d, 16);
                        nv[cc] = d * eE[u][cc];
                    }
                    w0 = m ? nv[0] : w0;
                    w1 = m ? nv[1] : w1;
                    w2 = m ? nv[2] : w2;
                    float* wd = swbuf[(u & 1) ^ 1];
                    wd[j0] = w0; wd[j0 + 1] = w1; wd[j0 + 2] = w2;
                    __syncwarp();
                }
            }
            float s = __shfl_sync(0xffffffffu, w0, 0);   // >0 always
            C += __logf(s);
            carry_inv = __fdividef(1.0f, s);
        }
        f0 = w0 * carry_inv; f1 = w1 * carry_inv; f2 = w2 * carry_inv;
    } else {
        // ================ BACKWARD: v <- E (exp(e_t) . v), t = 511..256 ==========
        uint64_t Er[36];
        #pragma unroll
        for (int c = 0; c < 3; c++)
            #pragma unroll
            for (int k = 0; k < 12; k++)
                Er[c * 12 + k] = pack2(__expf(transitions[(3 * q + c) * NUM_TAGS + i0 + 2 * k]),
                                       __expf(transitions[(3 * q + c) * NUM_TAGS + i0 + 2 * k + 1]));

        float v0 = 1.0f, v1 = 1.0f, v2 = 1.0f;

        for (int c = 0; c < NCH; c++) {
            const int Tb = SEQ_LEN - CHUNK * (c + 1);     // chunk covers t = Tb..Tb+7
            // boundary emission (t = Tb-1) prefetch: off-chain LDG at chunk top
            float bE0 = __ldg(em_b + (size_t)(Tb - 1) * NUM_TAGS + j0);
            float bE1 = __ldg(em_b + (size_t)(Tb - 1) * NUM_TAGS + j0 + 1);
            float bE2 = __ldg(em_b + (size_t)(Tb - 1) * NUM_TAGS + j0 + 2);

            if (c + 1 < NCH) {
                uint32_t dst = (uint32_t)__cvta_generic_to_shared(&sem[(c + 1) & 1][0]);
                const float* src = em_b + (size_t)(Tb - CHUNK) * NUM_TAGS;
                #pragma unroll
                for (int r = 0; r < 3; r++)
                    cp16(dst + lane * 16 + r * 512, src + lane * 4 + r * 128);
            }
            asm volatile("cp.async.commit_group;");
            asm volatile("cp.async.wait_group 1;");
            __syncwarp();

            const float* eb = sem[c & 1];
            float eE[CHUNK][3];
            #pragma unroll
            for (int u = 0; u < CHUNK; u++) {
                eE[u][0] = __expf(eb[u * NUM_TAGS + j0]);
                eE[u][1] = __expf(eb[u * NUM_TAGS + j0 + 1]);
                eE[u][2] = __expf(eb[u * NUM_TAGS + j0 + 2]);
            }
            float eEp0 = __expf(bE0), eEp1 = __expf(bE1), eEp2 = __expf(bE2);

            if (c == 0) {   // init y_511 = exp(e_511) . 1
                swbuf[0][j0]     = eE[7][0];
                swbuf[0][j0 + 1] = eE[7][1];
                swbuf[0][j0 + 2] = eE[7][2];
                __syncwarp();
            }

            const int4 ma = ((const int4*)(smask + Tb))[0];
            const int4 mbq = ((const int4*)(smask + Tb))[1];
            const int mall = ma.x & ma.y & ma.z & ma.w & mbq.x & mbq.y & mbq.z & mbq.w;

            if (mall) {
                #pragma unroll
                for (int s = 0; s < CHUNK; s++) {
                    const int u = CHUNK - 1 - s;           // consume descending t
                    const ulonglong2* yv = (const ulonglong2*)(&swbuf[s & 1][i0]);
                    uint64_t a0[3] = {0,0,0}, a1[3] = {0,0,0};
                    #pragma unroll
                    for (int r = 0; r < 6; r++) {
                        ulonglong2 Y = yv[r];
                        #pragma unroll
                        for (int cc = 0; cc < 3; cc++) {
                            fma2(a0[cc], Y.x, Er[cc * 12 + 2 * r]);
                            fma2(a1[cc], Y.y, Er[cc * 12 + 2 * r + 1]);
                        }
                    }
                    float s0 = (u > 0) ? eE[u - 1][0] : eEp0;
                    float s1 = (u > 0) ? eE[u - 1][1] : eEp1;
                    float s2 = (u > 0) ? eE[u - 1][2] : eEp2;
                    float* yd = swbuf[(s & 1) ^ 1];
                    #pragma unroll
                    for (int cc = 0; cc < 3; cc++) {
                        uint64_t ss = add2(a0[cc], a1[cc]);
                        float d = lo2(ss) + hi2(ss);
                        d += __shfl_xor_sync(0xffffffffu, d, 16);
                        if (cc == 0) { v0 = d; yd[j0]     = s0 * d; }
                        else if (cc == 1) { v1 = d; yd[j0 + 1] = s1 * d; }
                        else { v2 = d; yd[j0 + 2] = s2 * d; }
                    }
                    asm volatile("" ::: "memory");
                }
            } else {
                #pragma unroll
                for (int s = 0; s < CHUNK; s++) {
                    const int u = CHUNK - 1 - s;
                    const ulonglong2* yv = (const ulonglong2*)(&swbuf[s & 1][i0]);
                    uint64_t a0[3] = {0,0,0}, a1[3] = {0,0,0};
                    #pragma unroll
                    for (int r = 0; r < 6; r++) {
                        ulonglong2 Y = yv[r];
                        #pragma unroll
                        for (int cc = 0; cc < 3; cc++) {
                            fma2(a0[cc], Y.x, Er[cc * 12 + 2 * r]);
                            fma2(a1[cc], Y.y, Er[cc * 12 + 2 * r + 1]);
                        }
                    }
                    int m = smask[Tb + u];
                    float nv[3];
                    #pragma unroll
                    for (int cc = 0; cc < 3; cc++) {
                        uint64_t ss = add2(a0[cc], a1[cc]);
                        float d = lo2(ss) + hi2(ss);
                        d += __shfl_xor_sync(0xffffffffu, d, 16);
                        nv[cc] = d;
                    }
                    v0 = m ? nv[0] : v0;
                    v1 = m ? nv[1] : v1;
                    v2 = m ? nv[2] : v2;
                    float s0 = (u > 0) ? eE[u - 1][0] : eEp0;
                    float s1 = (u > 0) ? eE[u - 1][1] : eEp1;
                    float s2 = (u > 0) ? eE[u - 1][2] : eEp2;
                    float* yd = swbuf[(s & 1) ^ 1];
                    yd[j0] = s0 * v0; yd[j0 + 1] = s1 * v1; yd[j0 + 2] = s2 * v2;
                    __syncwarp();
                }
            }

            // per-chunk renorm (v stays normalized; y rewritten consistently)
            float vs = (h == 0) ? (v0 + v1 + v2) : 0.0f;
            #pragma unroll
            for (int off = 16; off; off >>= 1)
                vs += __shfl_xor_sync(0xffffffffu, vs, off);
            C += __logf(vs);
            float inv = __fdividef(1.0f, vs);
            v0 *= inv; v1 *= inv; v2 *= inv;
            swbuf[0][j0]     = eEp0 * v0;
            swbuf[0][j0 + 1] = eEp1 * v1;
            swbuf[0][j0 + 2] = eEp2 * v2;
            __syncwarp();
        }
        f0 = v0; f1 = v1; f2 = v2;
    }

    // --- publish this half's partials ------------------------------------------------
    if (h == 0) {
        g_vec[b][half][j0]     = f0;
        g_vec[b][half][j0 + 1] = f1;
        g_vec[b][half][j0 + 2] = f2;
    }
    if (lane == 0) {
        g_part[b][half][0] = C;
        g_part[b][half][1] = sc;
    }

    // --- pair combine: second finisher computes logZ, then maybe the global mean -----
    unsigned turn = 0;
    if (lane == 0) {
        __threadfence();
        turn = atomicAdd(&g_pair[b], 1u);
    }
    turn = __shfl_sync(0xffffffffu, turn, 0);
    if (turn == 1) {
        __threadfence();
        float d = 0.0f;
        if (h == 0) {
            #pragma unroll
            for (int cc = 0; cc < 3; cc++)
                d += __ldcg(&g_vec[b][0][j0 + cc]) * __ldcg(&g_vec[b][1][j0 + cc]);
        }
        #pragma unroll
        for (int off = 16; off; off >>= 1)
            d += __shfl_xor_sync(0xffffffffu, d, off);

        unsigned dn = 0;
        if (lane == 0) {
            float logZ  = __ldcg(&g_part[b][0][0]) + __ldcg(&g_part[b][1][0]) + __logf(d);
            float score = __ldcg(&g_part[b][0][1]) + __ldcg(&g_part[b][1][1]);
            g_nll[b]  = logZ - score;
            g_pair[b] = 0;                 // reset for graph replay
            __threadfence();
            dn = atomicAdd(&g_count, 1u);
        }
        dn = __shfl_sync(0xffffffffu, dn, 0);
        if (dn == BATCH - 1) {
            __threadfence();
            float r = 0.0f;
            #pragma unroll
            for (int i = lane; i < BATCH; i += 32)
                r += __ldcg(&g_nll[i]);
            #pragma unroll
            for (int off = 16; off; off >>= 1)
                r += __shfl_xor_sync(0xffffffffu, r, off);
            if (lane == 0) {
                out[0] = r * (1.0f / (float)BATCH);
                g_count = 0;               // reset for graph replay
            }
        }
    }
}

extern "C" void kernel_launch(void* const* d_in, const int* in_sizes, int n_in,
                              void* d_out, int out_size)
{
    const float* emissions   = (const float*)d_in[0];
    const float* transitions = (const float*)d_in[1];
    const int*   tags        = (const int*)d_in[2];
    const int*   mask        = (const int*)d_in[3];
    float*       out         = (float*)d_out;

    crf_split_kernel<<<2 * BATCH, 32>>>(emissions, transitions, tags, mask, out);
}